// round 15
// baseline (speedup 1.0000x reference)
#include <cuda_runtime.h>
#include <cuda_fp16.h>
#include <math.h>

#define D 48
#define NMAX 100000
#define EMAX 1600000
#define G 64
#define HID 128
#define OUTD 12
#define NSTEPS 5
#define BN_EPS 1e-5f
#define SCAN_CHUNK 1024
#define NBMAX 128            // ceil(NMAX/SCAN_CHUNK) = 98 <= 128

// ---------------- static device scratch (no allocation allowed) ----------------
__device__ __align__(16) float  g_bufA[(size_t)NMAX * D];     // current node features (fp32)
__device__ __align__(16) float  g_Y[(size_t)2 * NMAX * D];    // Y0 | Y1 (fp32 self-terms)
__device__ __align__(16) __half g_Y2h[(size_t)NMAX * D];      // Y2 (gathered only -> fp16)
__device__ __align__(16) __half g_Zh[(size_t)NMAX * D];       // Z  (gathered only -> fp16)
__device__ __align__(16) __half g_Th[(size_t)NMAX * D];       // T  (gathered/reduced -> fp16)
__device__ int   g_rowptr[NMAX + 1];
__device__ int   g_cnt[NMAX];
__device__ float g_dinv[NMAX];
__device__ __align__(16) int2 g_epack[EMAX];                  // .x = col, .y = bits(weight)
__device__ float g_stats[2 * D];                              // sum | sumsq
__device__ float g_graph[G * D];
__device__ __align__(16) float g_Wpack[D * 3 * D];            // [k_in 0..47][j 0..143]
__device__ int   g_is64;                                      // 1 if index inputs are int64
__device__ int   g_bsum[NBMAX];
__device__ int   g_boff[NBMAX];

// ---------------- dtype detection ----------------
__global__ void k_detect(const int* __restrict__ ei32, int E) {
    __shared__ int sh[256];
    int tid = threadIdx.x;
    int acc = 0;
    for (int i = tid; i < 4096; i += 256) {
        long long w = (long long)i * (2LL * E / 4096);
        int idx = (int)(w | 1);               // odd position
        if (idx < 2 * E) acc |= ei32[idx];
    }
    sh[tid] = acc;
    __syncthreads();
    for (int off = 128; off > 0; off >>= 1) {
        if (tid < off) sh[tid] |= sh[tid + off];
        __syncthreads();
    }
    if (tid == 0) g_is64 = (sh[0] == 0) ? 1 : 0;
}

// ---------------- CSR build ----------------
__global__ void k_zero_cnt(int N) {
    int i = blockIdx.x * blockDim.x + threadIdx.x;
    if (i < N) g_cnt[i] = 0;
}

__global__ void k_count(const int* __restrict__ ei32, int E, int N) {
    int e = blockIdx.x * blockDim.x + threadIdx.x;
    if (e >= E) return;
    int r = g_is64 ? ei32[2 * e] : ei32[e];
    if ((unsigned)r < (unsigned)N) atomicAdd(&g_cnt[r], 1);
}

__global__ __launch_bounds__(256) void k_bsum(int N) {
    __shared__ int sh[256];
    int tid = threadIdx.x;
    int base = blockIdx.x * SCAN_CHUNK + tid * 4;
    int s = 0;
#pragma unroll
    for (int i = 0; i < 4; i++) {
        int idx = base + i;
        if (idx < N) s += g_cnt[idx];
    }
    sh[tid] = s;
    __syncthreads();
    for (int off = 128; off > 0; off >>= 1) {
        if (tid < off) sh[tid] += sh[tid + off];
        __syncthreads();
    }
    if (tid == 0) g_bsum[blockIdx.x] = sh[0];
}

__global__ __launch_bounds__(128) void k_scan_bsum(int NB, int N) {
    __shared__ int ps[128];
    int tid = threadIdx.x;
    int v = (tid < NB) ? g_bsum[tid] : 0;
    ps[tid] = v;
    __syncthreads();
    for (int off = 1; off < 128; off <<= 1) {
        int t = (tid >= off) ? ps[tid - off] : 0;
        __syncthreads();
        ps[tid] += t;
        __syncthreads();
    }
    if (tid < NB) g_boff[tid] = ps[tid] - v;   // exclusive
    if (tid == 127) g_rowptr[N] = ps[127];
}

__global__ __launch_bounds__(256) void k_rowptr(int N) {
    __shared__ int sh[256];
    int tid = threadIdx.x;
    int base = blockIdx.x * SCAN_CHUNK + tid * 4;
    int c0 = 0, c1 = 0, c2 = 0, c3 = 0;
    if (base + 0 < N) c0 = g_cnt[base + 0];
    if (base + 1 < N) c1 = g_cnt[base + 1];
    if (base + 2 < N) c2 = g_cnt[base + 2];
    if (base + 3 < N) c3 = g_cnt[base + 3];
    int tsum = c0 + c1 + c2 + c3;
    sh[tid] = tsum;
    __syncthreads();
    for (int off = 1; off < 256; off <<= 1) {
        int t = (tid >= off) ? sh[tid - off] : 0;
        __syncthreads();
        sh[tid] += t;
        __syncthreads();
    }
    int p = g_boff[blockIdx.x] + sh[tid] - tsum;
#pragma unroll
    for (int i = 0; i < 4; i++) {
        int idx = base + i;
        int c = (i == 0) ? c0 : (i == 1) ? c1 : (i == 2) ? c2 : c3;
        if (idx < N) {
            g_rowptr[idx] = p;
            g_dinv[idx] = (c > 0) ? rsqrtf((float)c) : 0.0f;
            g_cnt[idx] = 0;
            p += c;
        }
    }
}

__global__ void k_scatter(const int* __restrict__ ei32, int E, int N) {
    int e = blockIdx.x * blockDim.x + threadIdx.x;
    if (e >= E) return;
    int is64 = g_is64;
    int r = is64 ? ei32[2 * e]               : ei32[e];
    int c = is64 ? ei32[2 * ((size_t)E + e)] : ei32[(size_t)E + e];
    if ((unsigned)r >= (unsigned)N || (unsigned)c >= (unsigned)N) return;
    float w = -g_dinv[r] * g_dinv[c];
    int pos = g_rowptr[r] + atomicAdd(&g_cnt[r], 1);
    g_epack[pos] = make_int2(c, __float_as_int(w));
}

// packed weight [48][144]: cols 0..47 = W0-W2, 48..95 = W1, 96..143 = W2
__global__ void k_wpack(const float* __restrict__ W) {
    int idx = blockIdx.x * blockDim.x + threadIdx.x;
    if (idx >= D * 144) return;
    int i = idx / 144;
    int j = idx % 144;
    int k = j / D;
    int jj = j % D;
    float v = W[k * D * D + i * D + jj];
    if (k == 0) v -= W[2 * D * D + i * D + jj];
    g_Wpack[i * 144 + j] = v;
}

// ---------------- fused GEMM via fma.rn.f32x2: [Y0|Y1](fp32), Y2(fp16) ----------------
__global__ __launch_bounds__(128) void k_gemm(const float* __restrict__ xext, int useExt, int N) {
    __shared__ __align__(16) float Ws[D * 144];   // 27648 B
    int tid = threadIdx.x;
    if (blockIdx.x == 0 && tid < 2 * D) g_stats[tid] = 0.0f;   // zero BN stats for this step

    const float* in = useExt ? xext : g_bufA;
    for (int i = tid; i < D * 144; i += 128) Ws[i] = g_Wpack[i];
    __syncthreads();

    int node = blockIdx.x * 128 + tid;
    if (node >= N) return;

    unsigned long long xd[D];
    {
        const float* xrow = in + (size_t)node * D;
#pragma unroll
        for (int q = 0; q < D / 4; q++) {
            float4 v = *(const float4*)(xrow + q * 4);
            asm("mov.b64 %0, {%1, %1};" : "=l"(xd[q * 4 + 0]) : "f"(v.x));
            asm("mov.b64 %0, {%1, %1};" : "=l"(xd[q * 4 + 1]) : "f"(v.y));
            asm("mov.b64 %0, {%1, %1};" : "=l"(xd[q * 4 + 2]) : "f"(v.z));
            asm("mov.b64 %0, {%1, %1};" : "=l"(xd[q * 4 + 3]) : "f"(v.w));
        }
    }

#pragma unroll 2
    for (int jb = 0; jb < 24; jb++) {
        unsigned long long a0 = 0ull, a1 = 0ull;
        const ulonglong2* wp = (const ulonglong2*)(Ws + jb * 4);
#pragma unroll
        for (int k = 0; k < D; k++) {
            ulonglong2 w2 = wp[k * 36];     // row stride: 144 floats = 36 ulonglong2
            asm("fma.rn.f32x2 %0, %1, %2, %0;" : "+l"(a0) : "l"(xd[k]), "l"(w2.x));
            asm("fma.rn.f32x2 %0, %1, %2, %0;" : "+l"(a1) : "l"(xd[k]), "l"(w2.y));
        }
        int j = jb * 4;
        int r = j / D, cc = j % D;
        float o0, o1, o2, o3;
        asm("mov.b64 {%0, %1}, %2;" : "=f"(o0), "=f"(o1) : "l"(a0));
        asm("mov.b64 {%0, %1}, %2;" : "=f"(o2), "=f"(o3) : "l"(a1));
        *(float4*)&g_Y[((size_t)r * N + node) * D + cc] = make_float4(o0, o1, o2, o3);
    }
#pragma unroll 2
    for (int jb = 24; jb < 36; jb++) {
        unsigned long long a0 = 0ull, a1 = 0ull;
        const ulonglong2* wp = (const ulonglong2*)(Ws + jb * 4);
#pragma unroll
        for (int k = 0; k < D; k++) {
            ulonglong2 w2 = wp[k * 36];
            asm("fma.rn.f32x2 %0, %1, %2, %0;" : "+l"(a0) : "l"(xd[k]), "l"(w2.x));
            asm("fma.rn.f32x2 %0, %1, %2, %0;" : "+l"(a1) : "l"(xd[k]), "l"(w2.y));
        }
        int cc = jb * 4 - 96;
        float o0, o1, o2, o3;
        asm("mov.b64 {%0, %1}, %2;" : "=f"(o0), "=f"(o1) : "l"(a0));
        asm("mov.b64 {%0, %1}, %2;" : "=f"(o2), "=f"(o3) : "l"(a1));
        *(__half2*)&g_Y2h[(size_t)node * D + cc]     = __floats2half2_rn(o0, o1);
        *(__half2*)&g_Y2h[(size_t)node * D + cc + 2] = __floats2half2_rn(o2, o3);
    }
}

// ---------------- gather kernels: 192 threads; thread = (row-in-block, 4-col chunk) ----------------
// Simple per-edge loop (R12 style — the 4x unroll of R14 regressed).
__global__ __launch_bounds__(192) void k_L1(int N) {   // Zh = fp16(Y1 + 2*L(Y2h))
    int tid = threadIdx.x;
    int row = blockIdx.x * 16 + tid / 12;
    int c4 = (tid % 12) * 4;
    if (row >= N) return;
    const float* Y1 = g_Y + (size_t)1 * N * D;
    int s = g_rowptr[row], e = g_rowptr[row + 1];
    float ax = 0.f, ay = 0.f, az = 0.f, aw = 0.f;
    for (int p = s; p < e; p++) {
        int2 d = g_epack[p];
        float w = __int_as_float(d.y);
        uint2 hv = *(const uint2*)&g_Y2h[(size_t)d.x * D + c4];
        float2 f0 = __half22float2(*(__half2*)&hv.x);
        float2 f1 = __half22float2(*(__half2*)&hv.y);
        ax = fmaf(w, f0.x, ax); ay = fmaf(w, f0.y, ay);
        az = fmaf(w, f1.x, az); aw = fmaf(w, f1.y, aw);
    }
    float4 y1 = *(const float4*)&Y1[(size_t)row * D + c4];
    float zx = fmaf(2.f, ax, y1.x), zy = fmaf(2.f, ay, y1.y);
    float zz = fmaf(2.f, az, y1.z), zw = fmaf(2.f, aw, y1.w);
    *(__half2*)&g_Zh[(size_t)row * D + c4]     = __floats2half2_rn(zx, zy);
    *(__half2*)&g_Zh[(size_t)row * D + c4 + 2] = __floats2half2_rn(zz, zw);
}

__global__ __launch_bounds__(192) void k_L2(const float* __restrict__ bias, int N) {
    // Th = fp16(relu(Y0 + L(Zh) + b)) + fused BN-stat accumulation
    __shared__ float ssum[D], ssq[D];
    int tid = threadIdx.x;
    if (tid < D) { ssum[tid] = 0.f; ssq[tid] = 0.f; }
    __syncthreads();

    int row = blockIdx.x * 16 + tid / 12;
    int c4 = (tid % 12) * 4;
    float tx = 0.f, ty = 0.f, tz = 0.f, tw = 0.f;
    if (row < N) {
        int s = g_rowptr[row], e = g_rowptr[row + 1];
        float ax = 0.f, ay = 0.f, az = 0.f, aw = 0.f;
        for (int p = s; p < e; p++) {
            int2 d = g_epack[p];
            float w = __int_as_float(d.y);
            uint2 hv = *(const uint2*)&g_Zh[(size_t)d.x * D + c4];
            float2 f0 = __half22float2(*(__half2*)&hv.x);
            float2 f1 = __half22float2(*(__half2*)&hv.y);
            ax = fmaf(w, f0.x, ax); ay = fmaf(w, f0.y, ay);
            az = fmaf(w, f1.x, az); aw = fmaf(w, f1.y, aw);
        }
        float4 y0 = *(const float4*)&g_Y[(size_t)row * D + c4];
        tx = fmaxf(y0.x + ax + bias[c4 + 0], 0.f);
        ty = fmaxf(y0.y + ay + bias[c4 + 1], 0.f);
        tz = fmaxf(y0.z + az + bias[c4 + 2], 0.f);
        tw = fmaxf(y0.w + aw + bias[c4 + 3], 0.f);
        *(__half2*)&g_Th[(size_t)row * D + c4]     = __floats2half2_rn(tx, ty);
        *(__half2*)&g_Th[(size_t)row * D + c4 + 2] = __floats2half2_rn(tz, tw);
        // accumulate the fp16-rounded values (what BN will actually normalize)
        float2 r0 = __half22float2(__floats2half2_rn(tx, ty));
        float2 r1 = __half22float2(__floats2half2_rn(tz, tw));
        tx = r0.x; ty = r0.y; tz = r1.x; tw = r1.y;
    }
    atomicAdd(&ssum[c4 + 0], tx); atomicAdd(&ssq[c4 + 0], tx * tx);
    atomicAdd(&ssum[c4 + 1], ty); atomicAdd(&ssq[c4 + 1], ty * ty);
    atomicAdd(&ssum[c4 + 2], tz); atomicAdd(&ssq[c4 + 2], tz * tz);
    atomicAdd(&ssum[c4 + 3], tw); atomicAdd(&ssq[c4 + 3], tw * tw);
    __syncthreads();
    if (tid < D) {
        atomicAdd(&g_stats[tid], ssum[tid]);
        atomicAdd(&g_stats[D + tid], ssq[tid]);
    }
}

__global__ __launch_bounds__(192) void k_max(const float* __restrict__ gamma,
                                             const float* __restrict__ beta, int N) {
    // fused BN coefficient computation + segment_max of BN(Th); empty -> 0
    __shared__ float sscale[D], sshift[D];
    int tid = threadIdx.x;
    if (tid < D) {
        float inv = 1.0f / (float)N;
        float mean = g_stats[tid] * inv;
        float var = fmaxf(g_stats[D + tid] * inv - mean * mean, 0.0f);
        float sc = gamma[tid] * rsqrtf(var + BN_EPS);
        sscale[tid] = sc;
        sshift[tid] = beta[tid] - mean * sc;
    }
    __syncthreads();

    int row = blockIdx.x * 16 + tid / 12;
    int c4 = (tid % 12) * 4;
    if (row >= N) return;
    float scx = sscale[c4 + 0], scy = sscale[c4 + 1], scz = sscale[c4 + 2], scw = sscale[c4 + 3];
    float shx = sshift[c4 + 0], shy = sshift[c4 + 1], shz = sshift[c4 + 2], shw = sshift[c4 + 3];
    int s = g_rowptr[row], e = g_rowptr[row + 1];
    float mx = -INFINITY, my = -INFINITY, mz = -INFINITY, mw = -INFINITY;
    for (int p = s; p < e; p++) {
        int2 d = g_epack[p];
        uint2 hv = *(const uint2*)&g_Th[(size_t)d.x * D + c4];
        float2 f0 = __half22float2(*(__half2*)&hv.x);
        float2 f1 = __half22float2(*(__half2*)&hv.y);
        mx = fmaxf(mx, fmaf(scx, f0.x, shx));
        my = fmaxf(my, fmaf(scy, f0.y, shy));
        mz = fmaxf(mz, fmaf(scz, f1.x, shz));
        mw = fmaxf(mw, fmaf(scw, f1.y, shw));
    }
    float4 o = (s == e) ? make_float4(0.f, 0.f, 0.f, 0.f) : make_float4(mx, my, mz, mw);
    *(float4*)&g_bufA[(size_t)row * D + c4] = o;
}

// ---------------- pooling + MLP ----------------
__global__ void k_zero_graph() {
    int i = blockIdx.x * blockDim.x + threadIdx.x;
    if (i < G * D) g_graph[i] = 0.f;
}

__global__ __launch_bounds__(96) void k_pool(const int* __restrict__ batch32, int N) {
    int is64 = g_is64;
    int f = threadIdx.x % D;
    int sub = threadIdx.x / D;
    int n0 = blockIdx.x * 2048;
    int nend = min(n0 + 2048, N);
    float acc = 0.f;
    int curg = -1;
    for (int n = n0 + sub; n < nend; n += 2) {
        int g = is64 ? batch32[2 * n] : batch32[n];
        if ((unsigned)g >= (unsigned)G) continue;
        if (g != curg) {
            if (curg >= 0) atomicAdd(&g_graph[curg * D + f], acc);
            acc = 0.f;
            curg = g;
        }
        acc += g_bufA[(size_t)n * D + f];
    }
    if (curg >= 0) atomicAdd(&g_graph[curg * D + f], acc);
}

__global__ __launch_bounds__(256) void k_mlp(const float* __restrict__ W1, const float* __restrict__ b1,
                                             const float* __restrict__ W2, const float* __restrict__ b2,
                                             float* __restrict__ out) {
    __shared__ float gs[G * D];
    __shared__ float hs[G * HID];
    int tid = threadIdx.x;
    for (int i = tid; i < G * D; i += 256) gs[i] = g_graph[i];
    __syncthreads();
    for (int o = tid; o < G * HID; o += 256) {
        int gi = o / HID, j = o % HID;
        float a = b1[j];
#pragma unroll 8
        for (int k = 0; k < D; k++) a = fmaf(gs[gi * D + k], W1[k * HID + j], a);
        hs[o] = fmaxf(a, 0.f);
    }
    __syncthreads();
    for (int o = tid; o < G * OUTD; o += 256) {
        int gi = o / OUTD, j = o % OUTD;
        float a = b2[j];
#pragma unroll 8
        for (int k = 0; k < HID; k++) a = fmaf(hs[gi * HID + k], W2[k * OUTD + j], a);
        out[o] = a;
    }
}

// ---------------- launch ----------------
extern "C" void kernel_launch(void* const* d_in, const int* in_sizes, int n_in,
                              void* d_out, int out_size) {
    const float* x       = (const float*)d_in[0];
    const int*   ei32    = (const int*)d_in[1];
    const int*   batch32 = (const int*)d_in[2];

    int wb = 3;
    for (int i = 3; i < n_in; i++) {
        if (in_sizes[i] == 3 * D * D) { wb = i; break; }
    }
    const float* W     = (const float*)d_in[wb + 0];
    const float* b     = (const float*)d_in[wb + 1];
    const float* gamma = (const float*)d_in[wb + 2];
    const float* beta  = (const float*)d_in[wb + 3];
    const float* W1    = (const float*)d_in[wb + 4];
    const float* b1    = (const float*)d_in[wb + 5];
    const float* W2    = (const float*)d_in[wb + 6];
    const float* b2    = (const float*)d_in[wb + 7];
    float* out = (float*)d_out;

    int N = in_sizes[0] / D;
    int E = in_sizes[1] / 2;
    int NB = (N + SCAN_CHUNK - 1) / SCAN_CHUNK;

    // dtype detection + CSR build (hierarchical scan; dinv fused into phase C)
    k_detect<<<1, 256>>>(ei32, E);
    k_zero_cnt<<<(N + 255) / 256, 256>>>(N);
    k_count<<<(E + 255) / 256, 256>>>(ei32, E, N);
    k_bsum<<<NB, 256>>>(N);
    k_scan_bsum<<<1, 128>>>(NB, N);
    k_rowptr<<<NB, 256>>>(N);
    k_scatter<<<(E + 255) / 256, 256>>>(ei32, E, N);
    k_wpack<<<(D * 144 + 255) / 256, 256>>>(W);

    int gb = (N + 127) / 128;
    int rb = (N + 15) / 16;

    for (int step = 0; step < NSTEPS; step++) {
        k_gemm<<<gb, 128>>>(x, step == 0 ? 1 : 0, N);
        k_L1<<<rb, 192>>>(N);
        k_L2<<<rb, 192>>>(b, N);
        k_max<<<rb, 192>>>(gamma, beta, N);
    }

    k_zero_graph<<<(G * D + 255) / 256, 256>>>();
    k_pool<<<(N + 2047) / 2048, 96>>>(batch32, N);
    k_mlp<<<1, 256>>>(W1, b1, W2, b2, out);
}

// round 16
// speedup vs baseline: 1.0912x; 1.0912x over previous
#include <cuda_runtime.h>
#include <cuda_fp16.h>
#include <math.h>

#define D 48
#define NMAX 100000
#define EMAX 1600000
#define G 64
#define HID 128
#define OUTD 12
#define NSTEPS 5
#define BN_EPS 1e-5f
#define SCAN_CHUNK 1024
#define NBMAX 128            // ceil(NMAX/SCAN_CHUNK) = 98 <= 128

// ---------------- static device scratch (no allocation allowed) ----------------
__device__ __align__(16) float  g_bufA[(size_t)NMAX * D];     // current node features (fp32)
__device__ __align__(16) float  g_Y[(size_t)2 * NMAX * D];    // Y0 | Y1 (fp32 self-terms)
__device__ __align__(16) __half g_Y2h[(size_t)NMAX * D];      // Y2 (gathered only -> fp16)
__device__ __align__(16) __half g_Zh[(size_t)NMAX * D];       // Z  (gathered only -> fp16)
__device__ __align__(16) __half g_Th[(size_t)NMAX * D];       // T  (gathered/reduced -> fp16)
__device__ int   g_rowptr[NMAX + 1];
__device__ int   g_cnt[NMAX];
__device__ float g_dinv[NMAX];
__device__ int   g_ecol[EMAX];                                // neighbor index per CSR slot
__device__ float g_ew[EMAX];                                  // edge weight per CSR slot
__device__ float g_stats[2 * D];                              // sum | sumsq
__device__ float g_graph[G * D];
__device__ __align__(16) float g_Wpack[D * 3 * D];            // [k_in 0..47][j 0..143]
__device__ int   g_is64;                                      // 1 if index inputs are int64
__device__ int   g_bsum[NBMAX];
__device__ int   g_boff[NBMAX];

// ---------------- dtype detection ----------------
__global__ void k_detect(const int* __restrict__ ei32, int E) {
    __shared__ int sh[256];
    int tid = threadIdx.x;
    int acc = 0;
    for (int i = tid; i < 4096; i += 256) {
        long long w = (long long)i * (2LL * E / 4096);
        int idx = (int)(w | 1);               // odd position
        if (idx < 2 * E) acc |= ei32[idx];
    }
    sh[tid] = acc;
    __syncthreads();
    for (int off = 128; off > 0; off >>= 1) {
        if (tid < off) sh[tid] |= sh[tid + off];
        __syncthreads();
    }
    if (tid == 0) g_is64 = (sh[0] == 0) ? 1 : 0;
}

// ---------------- CSR build ----------------
__global__ void k_zero_cnt(int N) {
    int i = blockIdx.x * blockDim.x + threadIdx.x;
    if (i < N) g_cnt[i] = 0;
}

__global__ void k_count(const int* __restrict__ ei32, int E, int N) {
    int e = blockIdx.x * blockDim.x + threadIdx.x;
    if (e >= E) return;
    int r = g_is64 ? ei32[2 * e] : ei32[e];
    if ((unsigned)r < (unsigned)N) atomicAdd(&g_cnt[r], 1);
}

__global__ __launch_bounds__(256) void k_bsum(int N) {
    __shared__ int sh[256];
    int tid = threadIdx.x;
    int base = blockIdx.x * SCAN_CHUNK + tid * 4;
    int s = 0;
#pragma unroll
    for (int i = 0; i < 4; i++) {
        int idx = base + i;
        if (idx < N) s += g_cnt[idx];
    }
    sh[tid] = s;
    __syncthreads();
    for (int off = 128; off > 0; off >>= 1) {
        if (tid < off) sh[tid] += sh[tid + off];
        __syncthreads();
    }
    if (tid == 0) g_bsum[blockIdx.x] = sh[0];
}

__global__ __launch_bounds__(128) void k_scan_bsum(int NB, int N) {
    __shared__ int ps[128];
    int tid = threadIdx.x;
    int v = (tid < NB) ? g_bsum[tid] : 0;
    ps[tid] = v;
    __syncthreads();
    for (int off = 1; off < 128; off <<= 1) {
        int t = (tid >= off) ? ps[tid - off] : 0;
        __syncthreads();
        ps[tid] += t;
        __syncthreads();
    }
    if (tid < NB) g_boff[tid] = ps[tid] - v;   // exclusive
    if (tid == 127) g_rowptr[N] = ps[127];
}

__global__ __launch_bounds__(256) void k_rowptr(int N) {
    __shared__ int sh[256];
    int tid = threadIdx.x;
    int base = blockIdx.x * SCAN_CHUNK + tid * 4;
    int c0 = 0, c1 = 0, c2 = 0, c3 = 0;
    if (base + 0 < N) c0 = g_cnt[base + 0];
    if (base + 1 < N) c1 = g_cnt[base + 1];
    if (base + 2 < N) c2 = g_cnt[base + 2];
    if (base + 3 < N) c3 = g_cnt[base + 3];
    int tsum = c0 + c1 + c2 + c3;
    sh[tid] = tsum;
    __syncthreads();
    for (int off = 1; off < 256; off <<= 1) {
        int t = (tid >= off) ? sh[tid - off] : 0;
        __syncthreads();
        sh[tid] += t;
        __syncthreads();
    }
    int p = g_boff[blockIdx.x] + sh[tid] - tsum;
#pragma unroll
    for (int i = 0; i < 4; i++) {
        int idx = base + i;
        int c = (i == 0) ? c0 : (i == 1) ? c1 : (i == 2) ? c2 : c3;
        if (idx < N) {
            g_rowptr[idx] = p;
            g_dinv[idx] = (c > 0) ? rsqrtf((float)c) : 0.0f;
            g_cnt[idx] = 0;
            p += c;
        }
    }
}

__global__ void k_scatter(const int* __restrict__ ei32, int E, int N) {
    int e = blockIdx.x * blockDim.x + threadIdx.x;
    if (e >= E) return;
    int is64 = g_is64;
    int r = is64 ? ei32[2 * e]               : ei32[e];
    int c = is64 ? ei32[2 * ((size_t)E + e)] : ei32[(size_t)E + e];
    if ((unsigned)r >= (unsigned)N || (unsigned)c >= (unsigned)N) return;
    float w = -g_dinv[r] * g_dinv[c];
    int pos = g_rowptr[r] + atomicAdd(&g_cnt[r], 1);
    g_ecol[pos] = c;
    g_ew[pos] = w;
}

// packed weight [48][144]: cols 0..47 = W0-W2, 48..95 = W1, 96..143 = W2
__global__ void k_wpack(const float* __restrict__ W) {
    int idx = blockIdx.x * blockDim.x + threadIdx.x;
    if (idx >= D * 144) return;
    int i = idx / 144;
    int j = idx % 144;
    int k = j / D;
    int jj = j % D;
    float v = W[k * D * D + i * D + jj];
    if (k == 0) v -= W[2 * D * D + i * D + jj];
    g_Wpack[i * 144 + j] = v;
}

// ---------------- fused GEMM via fma.rn.f32x2: [Y0|Y1](fp32), Y2(fp16) ----------------
__global__ __launch_bounds__(128) void k_gemm(const float* __restrict__ xext, int useExt, int N) {
    __shared__ __align__(16) float Ws[D * 144];   // 27648 B
    int tid = threadIdx.x;
    if (blockIdx.x == 0 && tid < 2 * D) g_stats[tid] = 0.0f;   // zero BN stats for this step

    const float* in = useExt ? xext : g_bufA;
    for (int i = tid; i < D * 144; i += 128) Ws[i] = g_Wpack[i];
    __syncthreads();

    int node = blockIdx.x * 128 + tid;
    if (node >= N) return;

    unsigned long long xd[D];
    {
        const float* xrow = in + (size_t)node * D;
#pragma unroll
        for (int q = 0; q < D / 4; q++) {
            float4 v = *(const float4*)(xrow + q * 4);
            asm("mov.b64 %0, {%1, %1};" : "=l"(xd[q * 4 + 0]) : "f"(v.x));
            asm("mov.b64 %0, {%1, %1};" : "=l"(xd[q * 4 + 1]) : "f"(v.y));
            asm("mov.b64 %0, {%1, %1};" : "=l"(xd[q * 4 + 2]) : "f"(v.z));
            asm("mov.b64 %0, {%1, %1};" : "=l"(xd[q * 4 + 3]) : "f"(v.w));
        }
    }

#pragma unroll 2
    for (int jb = 0; jb < 24; jb++) {
        unsigned long long a0 = 0ull, a1 = 0ull;
        const ulonglong2* wp = (const ulonglong2*)(Ws + jb * 4);
#pragma unroll
        for (int k = 0; k < D; k++) {
            ulonglong2 w2 = wp[k * 36];     // row stride: 144 floats = 36 ulonglong2
            asm("fma.rn.f32x2 %0, %1, %2, %0;" : "+l"(a0) : "l"(xd[k]), "l"(w2.x));
            asm("fma.rn.f32x2 %0, %1, %2, %0;" : "+l"(a1) : "l"(xd[k]), "l"(w2.y));
        }
        int j = jb * 4;
        int r = j / D, cc = j % D;
        float o0, o1, o2, o3;
        asm("mov.b64 {%0, %1}, %2;" : "=f"(o0), "=f"(o1) : "l"(a0));
        asm("mov.b64 {%0, %1}, %2;" : "=f"(o2), "=f"(o3) : "l"(a1));
        *(float4*)&g_Y[((size_t)r * N + node) * D + cc] = make_float4(o0, o1, o2, o3);
    }
#pragma unroll 2
    for (int jb = 24; jb < 36; jb++) {
        unsigned long long a0 = 0ull, a1 = 0ull;
        const ulonglong2* wp = (const ulonglong2*)(Ws + jb * 4);
#pragma unroll
        for (int k = 0; k < D; k++) {
            ulonglong2 w2 = wp[k * 36];
            asm("fma.rn.f32x2 %0, %1, %2, %0;" : "+l"(a0) : "l"(xd[k]), "l"(w2.x));
            asm("fma.rn.f32x2 %0, %1, %2, %0;" : "+l"(a1) : "l"(xd[k]), "l"(w2.y));
        }
        int cc = jb * 4 - 96;
        float o0, o1, o2, o3;
        asm("mov.b64 {%0, %1}, %2;" : "=f"(o0), "=f"(o1) : "l"(a0));
        asm("mov.b64 {%0, %1}, %2;" : "=f"(o2), "=f"(o3) : "l"(a1));
        *(__half2*)&g_Y2h[(size_t)node * D + cc]     = __floats2half2_rn(o0, o1);
        *(__half2*)&g_Y2h[(size_t)node * D + cc + 2] = __floats2half2_rn(o2, o3);
    }
}

// ---------------- gather kernels: 192 threads; thread = (row-in-block, 4-col chunk) ----------------
__global__ __launch_bounds__(192) void k_L1(int N) {   // Zh = fp16(Y1 + 2*L(Y2h))
    int tid = threadIdx.x;
    int row = blockIdx.x * 16 + tid / 12;
    int c = tid % 12;
    if (row >= N) return;
    const float* Y1 = g_Y + (size_t)1 * N * D;
    int s = g_rowptr[row], e = g_rowptr[row + 1];
    float ax = 0.f, ay = 0.f, az = 0.f, aw = 0.f;
    for (int p = s; p < e; p++) {
        int col = g_ecol[p];
        float w = g_ew[p];
        uint2 hv = *(const uint2*)&g_Y2h[(size_t)col * D + c * 4];
        float2 f0 = __half22float2(*(__half2*)&hv.x);
        float2 f1 = __half22float2(*(__half2*)&hv.y);
        ax = fmaf(w, f0.x, ax); ay = fmaf(w, f0.y, ay);
        az = fmaf(w, f1.x, az); aw = fmaf(w, f1.y, aw);
    }
    float4 y1 = *(const float4*)&Y1[(size_t)row * D + c * 4];
    float zx = fmaf(2.f, ax, y1.x), zy = fmaf(2.f, ay, y1.y);
    float zz = fmaf(2.f, az, y1.z), zw = fmaf(2.f, aw, y1.w);
    *(__half2*)&g_Zh[(size_t)row * D + c * 4]     = __floats2half2_rn(zx, zy);
    *(__half2*)&g_Zh[(size_t)row * D + c * 4 + 2] = __floats2half2_rn(zz, zw);
}

__global__ __launch_bounds__(192) void k_L2(const float* __restrict__ bias, int N) {
    // Th = fp16(relu(Y0 + L(Zh) + b))
    int tid = threadIdx.x;
    int row = blockIdx.x * 16 + tid / 12;
    int c = tid % 12;
    if (row >= N) return;
    int s = g_rowptr[row], e = g_rowptr[row + 1];
    float ax = 0.f, ay = 0.f, az = 0.f, aw = 0.f;
    for (int p = s; p < e; p++) {
        int col = g_ecol[p];
        float w = g_ew[p];
        uint2 hv = *(const uint2*)&g_Zh[(size_t)col * D + c * 4];
        float2 f0 = __half22float2(*(__half2*)&hv.x);
        float2 f1 = __half22float2(*(__half2*)&hv.y);
        ax = fmaf(w, f0.x, ax); ay = fmaf(w, f0.y, ay);
        az = fmaf(w, f1.x, az); aw = fmaf(w, f1.y, aw);
    }
    float4 y0 = *(const float4*)&g_Y[(size_t)row * D + c * 4];
    float tx = fmaxf(y0.x + ax + bias[c * 4 + 0], 0.f);
    float ty = fmaxf(y0.y + ay + bias[c * 4 + 1], 0.f);
    float tz = fmaxf(y0.z + az + bias[c * 4 + 2], 0.f);
    float tw = fmaxf(y0.w + aw + bias[c * 4 + 3], 0.f);
    *(__half2*)&g_Th[(size_t)row * D + c * 4]     = __floats2half2_rn(tx, ty);
    *(__half2*)&g_Th[(size_t)row * D + c * 4 + 2] = __floats2half2_rn(tz, tw);
}

// BN stats over fp16 T, accumulated in fp32 (coalesced, contention-free)
__global__ __launch_bounds__(192) void k_stats(int N) {
    __shared__ float sh[2 * 192];
    int tid = threadIdx.x;
    int f = tid % D;
    int grp = tid / D;
    int n0 = blockIdx.x * 1024;
    int nend = min(n0 + 1024, N);
    float s = 0.f, q = 0.f;
    for (int n = n0 + grp; n < nend; n += 4) {
        float v = __half2float(g_Th[(size_t)n * D + f]);
        s += v;
        q = fmaf(v, v, q);
    }
    sh[tid] = s;
    sh[192 + tid] = q;
    __syncthreads();
    if (tid < D) {
        float ts = 0.f, tq = 0.f;
#pragma unroll
        for (int g2 = 0; g2 < 4; g2++) {
            ts += sh[g2 * D + tid];
            tq += sh[192 + g2 * D + tid];
        }
        atomicAdd(&g_stats[tid], ts);
        atomicAdd(&g_stats[D + tid], tq);
    }
}

__global__ __launch_bounds__(192) void k_max(const float* __restrict__ gamma,
                                             const float* __restrict__ beta, int N) {
    // fused BN coefficient computation (per-block, no atomics) + segment_max of BN(Th)
    __shared__ float sscale[D], sshift[D];
    int tid = threadIdx.x;
    if (tid < D) {
        float inv = 1.0f / (float)N;
        float mean = g_stats[tid] * inv;
        float var = fmaxf(g_stats[D + tid] * inv - mean * mean, 0.0f);
        float sc = gamma[tid] * rsqrtf(var + BN_EPS);
        sscale[tid] = sc;
        sshift[tid] = beta[tid] - mean * sc;
    }
    __syncthreads();

    int row = blockIdx.x * 16 + tid / 12;
    int c = tid % 12;
    if (row >= N) return;
    float scx = sscale[c * 4 + 0], scy = sscale[c * 4 + 1];
    float scz = sscale[c * 4 + 2], scw = sscale[c * 4 + 3];
    float shx = sshift[c * 4 + 0], shy = sshift[c * 4 + 1];
    float shz = sshift[c * 4 + 2], shw = sshift[c * 4 + 3];
    int s = g_rowptr[row], e = g_rowptr[row + 1];
    float mx = -INFINITY, my = -INFINITY, mz = -INFINITY, mw = -INFINITY;
    for (int p = s; p < e; p++) {
        int col = g_ecol[p];
        uint2 hv = *(const uint2*)&g_Th[(size_t)col * D + c * 4];
        float2 f0 = __half22float2(*(__half2*)&hv.x);
        float2 f1 = __half22float2(*(__half2*)&hv.y);
        mx = fmaxf(mx, fmaf(scx, f0.x, shx));
        my = fmaxf(my, fmaf(scy, f0.y, shy));
        mz = fmaxf(mz, fmaf(scz, f1.x, shz));
        mw = fmaxf(mw, fmaf(scw, f1.y, shw));
    }
    float4 o = (s == e) ? make_float4(0.f, 0.f, 0.f, 0.f) : make_float4(mx, my, mz, mw);
    *(float4*)&g_bufA[(size_t)row * D + c * 4] = o;
}

// ---------------- pooling + MLP ----------------
__global__ void k_zero_graph() {
    int i = blockIdx.x * blockDim.x + threadIdx.x;
    if (i < G * D) g_graph[i] = 0.f;
}

__global__ __launch_bounds__(96) void k_pool(const int* __restrict__ batch32, int N) {
    int is64 = g_is64;
    int f = threadIdx.x % D;
    int sub = threadIdx.x / D;
    int n0 = blockIdx.x * 2048;
    int nend = min(n0 + 2048, N);
    float acc = 0.f;
    int curg = -1;
    for (int n = n0 + sub; n < nend; n += 2) {
        int g = is64 ? batch32[2 * n] : batch32[n];
        if ((unsigned)g >= (unsigned)G) continue;
        if (g != curg) {
            if (curg >= 0) atomicAdd(&g_graph[curg * D + f], acc);
            acc = 0.f;
            curg = g;
        }
        acc += g_bufA[(size_t)n * D + f];
    }
    if (curg >= 0) atomicAdd(&g_graph[curg * D + f], acc);
}

__global__ __launch_bounds__(256) void k_mlp(const float* __restrict__ W1, const float* __restrict__ b1,
                                             const float* __restrict__ W2, const float* __restrict__ b2,
                                             float* __restrict__ out) {
    __shared__ float gs[G * D];
    __shared__ float hs[G * HID];
    int tid = threadIdx.x;
    for (int i = tid; i < G * D; i += 256) gs[i] = g_graph[i];
    __syncthreads();
    for (int o = tid; o < G * HID; o += 256) {
        int gi = o / HID, j = o % HID;
        float a = b1[j];
#pragma unroll 8
        for (int k = 0; k < D; k++) a = fmaf(gs[gi * D + k], W1[k * HID + j], a);
        hs[o] = fmaxf(a, 0.f);
    }
    __syncthreads();
    for (int o = tid; o < G * OUTD; o += 256) {
        int gi = o / OUTD, j = o % OUTD;
        float a = b2[j];
#pragma unroll 8
        for (int k = 0; k < HID; k++) a = fmaf(hs[gi * HID + k], W2[k * OUTD + j], a);
        out[o] = a;
    }
}

// ---------------- launch ----------------
extern "C" void kernel_launch(void* const* d_in, const int* in_sizes, int n_in,
                              void* d_out, int out_size) {
    const float* x       = (const float*)d_in[0];
    const int*   ei32    = (const int*)d_in[1];
    const int*   batch32 = (const int*)d_in[2];

    int wb = 3;
    for (int i = 3; i < n_in; i++) {
        if (in_sizes[i] == 3 * D * D) { wb = i; break; }
    }
    const float* W     = (const float*)d_in[wb + 0];
    const float* b     = (const float*)d_in[wb + 1];
    const float* gamma = (const float*)d_in[wb + 2];
    const float* beta  = (const float*)d_in[wb + 3];
    const float* W1    = (const float*)d_in[wb + 4];
    const float* b1    = (const float*)d_in[wb + 5];
    const float* W2    = (const float*)d_in[wb + 6];
    const float* b2    = (const float*)d_in[wb + 7];
    float* out = (float*)d_out;

    int N = in_sizes[0] / D;
    int E = in_sizes[1] / 2;
    int NB = (N + SCAN_CHUNK - 1) / SCAN_CHUNK;

    // dtype detection + CSR build (hierarchical scan; dinv fused into phase C)
    k_detect<<<1, 256>>>(ei32, E);
    k_zero_cnt<<<(N + 255) / 256, 256>>>(N);
    k_count<<<(E + 255) / 256, 256>>>(ei32, E, N);
    k_bsum<<<NB, 256>>>(N);
    k_scan_bsum<<<1, 128>>>(NB, N);
    k_rowptr<<<NB, 256>>>(N);
    k_scatter<<<(E + 255) / 256, 256>>>(ei32, E, N);
    k_wpack<<<(D * 144 + 255) / 256, 256>>>(W);

    int gb = (N + 127) / 128;
    int rb = (N + 15) / 16;
    int sb = (N + 1023) / 1024;

    for (int step = 0; step < NSTEPS; step++) {
        k_gemm<<<gb, 128>>>(x, step == 0 ? 1 : 0, N);
        k_L1<<<rb, 192>>>(N);
        k_L2<<<rb, 192>>>(b, N);
        k_stats<<<sb, 192>>>(N);
        k_max<<<rb, 192>>>(gamma, beta, N);
    }

    k_zero_graph<<<(G * D + 255) / 256, 256>>>();
    k_pool<<<(N + 2047) / 2048, 96>>>(batch32, N);
    k_mlp<<<1, 256>>>(W1, b1, W2, b2, out);
}